// round 4
// baseline (speedup 1.0000x reference)
#include <cuda_runtime.h>
#include <math.h>
#include <stdint.h>

// Problem constants
#define B_   4
#define S_   1024
#define E_   256
#define H_   32
#define DK_  8
#define NQ_  8
#define FF_  1024
#define M_   (B_ * S_)   // 4096

typedef unsigned long long ULL;

// ---------------- f32x2 packed math helpers (PTX-only on sm_103a) ----------
__device__ __forceinline__ ULL fma2(ULL a, ULL b, ULL c) {
    ULL d; asm("fma.rn.f32x2 %0, %1, %2, %3;" : "=l"(d) : "l"(a), "l"(b), "l"(c)); return d;
}
__device__ __forceinline__ ULL mul2(ULL a, ULL b) {
    ULL d; asm("mul.rn.f32x2 %0, %1, %2;" : "=l"(d) : "l"(a), "l"(b)); return d;
}
__device__ __forceinline__ ULL add2(ULL a, ULL b) {
    ULL d; asm("add.rn.f32x2 %0, %1, %2;" : "=l"(d) : "l"(a), "l"(b)); return d;
}
__device__ __forceinline__ ULL pk(float lo, float hi) {
    ULL r; asm("mov.b64 %0, {%1, %2};" : "=l"(r) : "f"(lo), "f"(hi)); return r;
}
__device__ __forceinline__ void unpk(ULL v, float& lo, float& hi) {
    asm("mov.b64 {%0, %1}, %2;" : "=f"(lo), "=f"(hi) : "l"(v));
}
__device__ __forceinline__ float ex2f_(float x) {
    float y; asm("ex2.approx.f32 %0, %1;" : "=f"(y) : "f"(x)); return y;
}

// ---------------- scratch (device globals; no runtime allocation) ----------
__device__ __align__(16) float g_qout[M_ * E_];
__device__ __align__(16) float g_qkv[M_ * 3 * E_];
__device__ __align__(16) float g_ctx[M_ * E_];
__device__ __align__(16) float g_Wf[E_ * E_];
__device__ __align__(16) float g_bf[E_];
__device__ __align__(16) float g_tmp[M_ * E_];
__device__ __align__(16) float g_h[M_ * E_];
__device__ __align__(16) float g_qf[M_ * NQ_];
__device__ __align__(16) float g_hidden[M_ * FF_];
// split-K attention partials (no-max softmax: only l and acc needed)
// index: ((bh*4 + kq)*2 + qh)*256 + t   (query pair (qh*512+t, qh*512+t+256))
__device__ __align__(16) ULL g_pl[128 * 4 * 512];          // packed (l_q0, l_q1)
__device__ __align__(16) ULL g_pacc[(size_t)128 * 4 * 512 * 8]; // 8 packed channels

// ---------------- q_out = cos(x + theta[e % 8]), float4 --------------------
__global__ __launch_bounds__(256) void cos_encode_kernel(
    const float* __restrict__ x, const float* __restrict__ theta)
{
    int i = (blockIdx.x * 256 + threadIdx.x) * 4;
    float4 v = *(const float4*)(x + i);
    int j = i & 7;
    v.x = __cosf(v.x + theta[j + 0]);
    v.y = __cosf(v.y + theta[j + 1]);
    v.z = __cosf(v.z + theta[j + 2]);
    v.w = __cosf(v.w + theta[j + 3]);
    *(float4*)(g_qout + i) = v;
}

// ---------------- fold: Wf = w_comb @ w_out, bf = w_comb@b_out + b_comb -----
__global__ __launch_bounds__(256) void fold_w_kernel(
    const float* __restrict__ w_comb, const float* __restrict__ w_out,
    const float* __restrict__ b_out, const float* __restrict__ b_comb)
{
    int i = blockIdx.x;
    int j = threadIdx.x;
    float s = 0.f;
    #pragma unroll 8
    for (int k = 0; k < E_; k++)
        s = fmaf(w_comb[i * E_ + k], w_out[k * E_ + j], s);
    g_Wf[i * E_ + j] = s;

    __shared__ float red[256];
    red[j] = w_comb[i * E_ + j] * b_out[j];
    __syncthreads();
    #pragma unroll
    for (int off = 128; off > 0; off >>= 1) {
        if (j < off) red[j] += red[j + off];
        __syncthreads();
    }
    if (j == 0) g_bf[i] = red[0] + b_comb[i];
}

// ---------------- f32x2 SGEMM: C[M,N] = A[M,K] @ Bw[N,K]^T + bias ----------
// BM=128, BN=64, BK=16, 256 threads, 8x4 microtile; B stored duplicated-packed.
__global__ __launch_bounds__(256) void sgemm2_kernel(
    const float* __restrict__ A, const float* __restrict__ Bw,
    const float* __restrict__ bias, float* __restrict__ C,
    int M, int N, int K, int relu)
{
    __shared__ float As[16][132];
    __shared__ ULL   Bsd[16][66];   // duplicated (b,b) pairs

    int tid = threadIdx.x;
    int bm = blockIdx.y * 128;
    int bn = blockIdx.x * 64;
    int ty = tid >> 4;
    int tx = tid & 15;

    int alr = tid >> 1;
    int alc = (tid & 1) * 8;
    int blr = tid >> 2;
    int blc = (tid & 3) * 4;

    const float* Aptr = A  + (size_t)(bm + alr) * K + alc;
    const float* Bptr = Bw + (size_t)(bn + blr) * K + blc;

    float4 a0 = *(const float4*)(Aptr);
    float4 a1 = *(const float4*)(Aptr + 4);
    float4 b0 = *(const float4*)(Bptr);

    ULL acc[4][4];
    #pragma unroll
    for (int r = 0; r < 4; r++)
        #pragma unroll
        for (int j = 0; j < 4; j++) acc[r][j] = 0ULL;

    for (int k0 = 0; ; k0 += 16) {
        As[alc + 0][alr] = a0.x; As[alc + 1][alr] = a0.y;
        As[alc + 2][alr] = a0.z; As[alc + 3][alr] = a0.w;
        As[alc + 4][alr] = a1.x; As[alc + 5][alr] = a1.y;
        As[alc + 6][alr] = a1.z; As[alc + 7][alr] = a1.w;
        Bsd[blc + 0][blr] = pk(b0.x, b0.x);
        Bsd[blc + 1][blr] = pk(b0.y, b0.y);
        Bsd[blc + 2][blr] = pk(b0.z, b0.z);
        Bsd[blc + 3][blr] = pk(b0.w, b0.w);
        __syncthreads();

        bool last = (k0 + 16 >= K);
        if (!last) {
            Aptr += 16; Bptr += 16;
            a0 = *(const float4*)(Aptr);
            a1 = *(const float4*)(Aptr + 4);
            b0 = *(const float4*)(Bptr);
        }

        #pragma unroll
        for (int kk = 0; kk < 16; kk++) {
            ulonglong2 am0 = *(const ulonglong2*)&As[kk][ty * 8];
            ulonglong2 am1 = *(const ulonglong2*)&As[kk][ty * 8 + 4];
            ulonglong2 bb01 = *(const ulonglong2*)&Bsd[kk][tx * 4];
            ulonglong2 bb23 = *(const ulonglong2*)&Bsd[kk][tx * 4 + 2];
            ULL am[4] = {am0.x, am0.y, am1.x, am1.y};
            #pragma unroll
            for (int r = 0; r < 4; r++) {
                acc[r][0] = fma2(am[r], bb01.x, acc[r][0]);
                acc[r][1] = fma2(am[r], bb01.y, acc[r][1]);
                acc[r][2] = fma2(am[r], bb23.x, acc[r][2]);
                acc[r][3] = fma2(am[r], bb23.y, acc[r][3]);
            }
        }
        if (last) break;
        __syncthreads();
    }

    int col = bn + tx * 4;
    float4 bb = *(const float4*)(bias + col);
    #pragma unroll
    for (int r = 0; r < 4; r++) {
        float lo0, hi0, lo1, hi1, lo2v, hi2, lo3, hi3;
        unpk(acc[r][0], lo0, hi0);
        unpk(acc[r][1], lo1, hi1);
        unpk(acc[r][2], lo2v, hi2);
        unpk(acc[r][3], lo3, hi3);
        int row0 = bm + ty * 8 + 2 * r;
        float4 v;
        v.x = lo0 + bb.x; v.y = lo1 + bb.y; v.z = lo2v + bb.z; v.w = lo3 + bb.w;
        if (relu) { v.x = fmaxf(v.x, 0.f); v.y = fmaxf(v.y, 0.f);
                    v.z = fmaxf(v.z, 0.f); v.w = fmaxf(v.w, 0.f); }
        *(float4*)(C + (size_t)row0 * N + col) = v;
        v.x = hi0 + bb.x; v.y = hi1 + bb.y; v.z = hi2 + bb.z; v.w = hi3 + bb.w;
        if (relu) { v.x = fmaxf(v.x, 0.f); v.y = fmaxf(v.y, 0.f);
                    v.z = fmaxf(v.z, 0.f); v.w = fmaxf(v.w, 0.f); }
        *(float4*)(C + (size_t)(row0 + 1) * N + col) = v;
    }
}

// ---------------- attention pass 1: split-K, NO-MAX softmax, query-packed ---
// grid = (4 key-quarters, 2 query-halves, 128 bh), 256 threads.
// Scores bounded (|d| < ~8 in log2 domain) so exp2 never overflows; running
// max/rescale dropped entirely. K and V stored DUPLICATED (k,k) in smem so
// dot of two queries is computed fully packed with no horizontal sum.
__global__ __launch_bounds__(256) void attn_p1_kernel()
{
    __shared__ ULL Kd[256 * 8];   // 16 KB: channel c of key s at Kd[s*8+c], (k,k)
    __shared__ ULL Vd[256 * 8];   // 16 KB

    int kq = blockIdx.x;
    int qh = blockIdx.y;
    int bh = blockIdx.z;
    int b = bh >> 5;
    int h = bh & 31;
    int tid = threadIdx.x;
    const float* base = g_qkv + (size_t)b * S_ * (3 * E_) + h * DK_;

    // stage: each thread handles half a key (4 channels), 2 keys
    #pragma unroll
    for (int rep = 0; rep < 2; rep++) {
        int sk   = rep * 128 + (tid >> 1);
        int half = tid & 1;
        const float* rowp = base + (size_t)(kq * 256 + sk) * (3 * E_);
        float4 k = *(const float4*)(rowp + E_ + half * 4);
        float4 v = *(const float4*)(rowp + 2 * E_ + half * 4);
        ulonglong2* kr = (ulonglong2*)(Kd + sk * 8 + half * 4);
        ulonglong2* vr = (ulonglong2*)(Vd + sk * 8 + half * 4);
        kr[0] = make_ulonglong2(pk(k.x, k.x), pk(k.y, k.y));
        kr[1] = make_ulonglong2(pk(k.z, k.z), pk(k.w, k.w));
        vr[0] = make_ulonglong2(pk(v.x, v.x), pk(v.y, v.y));
        vr[1] = make_ulonglong2(pk(v.z, v.z), pk(v.w, v.w));
    }
    __syncthreads();

    const float qscale = 0.35355339059327373f * 1.4426950408889634f; // log2e/sqrt(8)
    int qi0 = qh * 512 + tid;
    int qi1 = qi0 + 256;

    // q packed ACROSS queries: q[c] = (q0[c], q1[c])
    ULL q[8];
    {
        const float4* p0 = (const float4*)(base + (size_t)qi0 * (3 * E_));
        const float4* p1 = (const float4*)(base + (size_t)qi1 * (3 * E_));
        float4 t0 = p0[0], t1 = p0[1], u0 = p1[0], u1 = p1[1];
        q[0] = pk(t0.x * qscale, u0.x * qscale);
        q[1] = pk(t0.y * qscale, u0.y * qscale);
        q[2] = pk(t0.z * qscale, u0.z * qscale);
        q[3] = pk(t0.w * qscale, u0.w * qscale);
        q[4] = pk(t1.x * qscale, u1.x * qscale);
        q[5] = pk(t1.y * qscale, u1.y * qscale);
        q[6] = pk(t1.z * qscale, u1.z * qscale);
        q[7] = pk(t1.w * qscale, u1.w * qscale);
    }

    ULL l = 0ULL;
    ULL acc[8];
    #pragma unroll
    for (int c = 0; c < 8; c++) acc[c] = 0ULL;

    #pragma unroll 2
    for (int s = 0; s < 256; s++) {
        const ulonglong2* kr = (const ulonglong2*)(Kd + s * 8);
        ulonglong2 k01 = kr[0], k23 = kr[1], k45 = kr[2], k67 = kr[3];
        ULL t = mul2(q[0], k01.x);
        t = fma2(q[1], k01.y, t);
        t = fma2(q[2], k23.x, t);
        t = fma2(q[3], k23.y, t);
        t = fma2(q[4], k45.x, t);
        t = fma2(q[5], k45.y, t);
        t = fma2(q[6], k67.x, t);
        t = fma2(q[7], k67.y, t);

        float d0, d1;
        unpk(t, d0, d1);
        ULL pp = pk(ex2f_(d0), ex2f_(d1));   // unnormalized softmax weights
        l = add2(l, pp);

        const ulonglong2* vr = (const ulonglong2*)(Vd + s * 8);
        ulonglong2 v01 = vr[0], v23 = vr[1], v45 = vr[2], v67 = vr[3];
        acc[0] = fma2(pp, v01.x, acc[0]);
        acc[1] = fma2(pp, v01.y, acc[1]);
        acc[2] = fma2(pp, v23.x, acc[2]);
        acc[3] = fma2(pp, v23.y, acc[3]);
        acc[4] = fma2(pp, v45.x, acc[4]);
        acc[5] = fma2(pp, v45.y, acc[5]);
        acc[6] = fma2(pp, v67.x, acc[6]);
        acc[7] = fma2(pp, v67.y, acc[7]);
    }

    // write partials
    int pidx = ((bh * 4 + kq) * 2 + qh) * 256 + tid;
    g_pl[pidx] = l;
    ulonglong2* pa = (ulonglong2*)(g_pacc + (size_t)pidx * 8);
    pa[0] = make_ulonglong2(acc[0], acc[1]);
    pa[1] = make_ulonglong2(acc[2], acc[3]);
    pa[2] = make_ulonglong2(acc[4], acc[5]);
    pa[3] = make_ulonglong2(acc[6], acc[7]);
}

// ---------------- attention pass 2: sum 4 partials, normalize ---------------
__global__ __launch_bounds__(256) void attn_p2_kernel()
{
    int idx = blockIdx.x * 256 + threadIdx.x;   // 65536 = 128 bh * 512 pq
    int bh = idx >> 9;
    int pq = idx & 511;         // qh*256 + t
    int b = bh >> 5;
    int h = bh & 31;

    ULL l = 0ULL;
    ULL c[8];
    #pragma unroll
    for (int j = 0; j < 8; j++) c[j] = 0ULL;

    #pragma unroll
    for (int kq = 0; kq < 4; kq++) {
        int p = bh * 2048 + kq * 512 + pq;
        l = add2(l, g_pl[p]);
        const ulonglong2* pa = (const ulonglong2*)(g_pacc + (size_t)p * 8);
        ulonglong2 a0 = pa[0], a1 = pa[1], a2 = pa[2], a3 = pa[3];
        c[0] = add2(c[0], a0.x); c[1] = add2(c[1], a0.y);
        c[2] = add2(c[2], a1.x); c[3] = add2(c[3], a1.y);
        c[4] = add2(c[4], a2.x); c[5] = add2(c[5], a2.y);
        c[6] = add2(c[6], a3.x); c[7] = add2(c[7], a3.y);
    }

    float L0, L1;
    unpk(l, L0, L1);
    float r0 = 1.f / L0, r1 = 1.f / L1;

    int qi0 = (pq >> 8) * 512 + (pq & 255);
    int qi1 = qi0 + 256;
    float* o0 = g_ctx + ((size_t)b * S_ + qi0) * E_ + h * DK_;
    float* o1 = g_ctx + ((size_t)b * S_ + qi1) * E_ + h * DK_;

    float x0[8], x1[8];
    #pragma unroll
    for (int j = 0; j < 8; j++) unpk(c[j], x0[j], x1[j]);
    float4 w;
    w.x = x0[0]*r0; w.y = x0[1]*r0; w.z = x0[2]*r0; w.w = x0[3]*r0;
    *(float4*)(o0) = w;
    w.x = x0[4]*r0; w.y = x0[5]*r0; w.z = x0[6]*r0; w.w = x0[7]*r0;
    *(float4*)(o0 + 4) = w;
    w.x = x1[0]*r1; w.y = x1[1]*r1; w.z = x1[2]*r1; w.w = x1[3]*r1;
    *(float4*)(o1) = w;
    w.x = x1[4]*r1; w.y = x1[5]*r1; w.z = x1[6]*r1; w.w = x1[7]*r1;
    *(float4*)(o1 + 4) = w;
}

// ---------------- layernorm: out = LN(a + b) * g + beta  (warp per row) -----
__global__ __launch_bounds__(256) void ln_kernel(
    const float* __restrict__ a, const float* __restrict__ bsrc,
    const float* __restrict__ g, const float* __restrict__ beta,
    float* __restrict__ out)
{
    int row  = (blockIdx.x * 256 + threadIdx.x) >> 5;
    int lane = threadIdx.x & 31;
    size_t off = (size_t)row * E_ + lane * 8;

    const float4* ap = (const float4*)(a + off);
    const float4* bp = (const float4*)(bsrc + off);
    float4 a0 = ap[0], a1 = ap[1], b0 = bp[0], b1 = bp[1];
    float v[8];
    v[0] = a0.x + b0.x; v[1] = a0.y + b0.y; v[2] = a0.z + b0.z; v[3] = a0.w + b0.w;
    v[4] = a1.x + b1.x; v[5] = a1.y + b1.y; v[6] = a1.z + b1.z; v[7] = a1.w + b1.w;

    float s = 0.f, ss = 0.f;
    #pragma unroll
    for (int i = 0; i < 8; i++) { s += v[i]; ss = fmaf(v[i], v[i], ss); }
    #pragma unroll
    for (int o = 16; o > 0; o >>= 1) {
        s  += __shfl_xor_sync(0xFFFFFFFFu, s,  o);
        ss += __shfl_xor_sync(0xFFFFFFFFu, ss, o);
    }
    float mu  = s * (1.f / E_);
    float var = ss * (1.f / E_) - mu * mu;
    float rs  = rsqrtf(var + 1e-5f);

    const float4* gp  = (const float4*)(g    + lane * 8);
    const float4* bep = (const float4*)(beta + lane * 8);
    float4 g0 = gp[0], g1v = gp[1], e0 = bep[0], e1 = bep[1];

    float4 w;
    w.x = (v[0]-mu)*rs*g0.x + e0.x; w.y = (v[1]-mu)*rs*g0.y + e0.y;
    w.z = (v[2]-mu)*rs*g0.z + e0.z; w.w = (v[3]-mu)*rs*g0.w + e0.w;
    *(float4*)(out + off) = w;
    w.x = (v[4]-mu)*rs*g1v.x + e1.x; w.y = (v[5]-mu)*rs*g1v.y + e1.y;
    w.z = (v[6]-mu)*rs*g1v.z + e1.z; w.w = (v[7]-mu)*rs*g1v.w + e1.w;
    *(float4*)(out + off + 4) = w;
}

// ---------------- qf = cos(theta_ffn) * cos(h @ w_ip^T + b_ip) --------------
__global__ __launch_bounds__(256) void qf_kernel(
    const float* __restrict__ w_ip, const float* __restrict__ b_ip,
    const float* __restrict__ theta_ffn)
{
    int m    = blockIdx.x;
    int j    = threadIdx.x >> 5;
    int lane = threadIdx.x & 31;
    const float* hr = g_h + (size_t)m * E_;
    const float* wr = w_ip + (size_t)j * E_;
    float s = 0.f;
    #pragma unroll
    for (int e = 0; e < E_; e += 32)
        s = fmaf(hr[e + lane], wr[e + lane], s);
    #pragma unroll
    for (int o = 16; o > 0; o >>= 1)
        s += __shfl_xor_sync(0xFFFFFFFFu, s, o);
    if (lane == 0)
        g_qf[m * NQ_ + j] = __cosf(theta_ffn[j]) * __cosf(s + b_ip[j]);
}

// ---------------- hidden = relu(qf @ w1^T + b1)   (K=8) ---------------------
__global__ __launch_bounds__(256) void hidden_kernel(
    const float* __restrict__ w1, const float* __restrict__ b1)
{
    int m = blockIdx.x >> 2;
    int f = ((blockIdx.x & 3) << 8) + threadIdx.x;
    const float* qr = g_qf + (size_t)m * NQ_;
    const float* wr = w1 + (size_t)f * NQ_;
    float s = b1[f];
    #pragma unroll
    for (int j = 0; j < NQ_; j++)
        s = fmaf(qr[j], wr[j], s);
    g_hidden[(size_t)m * FF_ + f] = fmaxf(s, 0.f);
}

// ---------------- launch ----------------------------------------------------
extern "C" void kernel_launch(void* const* d_in, const int* in_sizes, int n_in,
                              void* d_out, int out_size)
{
    (void)in_sizes; (void)n_in; (void)out_size;

    const float* x          = (const float*)d_in[0];
    const float* theta_attn = (const float*)d_in[1];
    const float* w_in       = (const float*)d_in[2];
    const float* b_in       = (const float*)d_in[3];
    const float* w_out      = (const float*)d_in[4];
    const float* b_out      = (const float*)d_in[5];
    const float* w_comb     = (const float*)d_in[6];
    const float* b_comb     = (const float*)d_in[7];
    const float* g1         = (const float*)d_in[8];
    const float* be1        = (const float*)d_in[9];
    const float* g2         = (const float*)d_in[10];
    const float* be2        = (const float*)d_in[11];
    const float* w_ip       = (const float*)d_in[12];
    const float* b_ip       = (const float*)d_in[13];
    const float* theta_ffn  = (const float*)d_in[14];
    const float* w1         = (const float*)d_in[15];
    const float* b1         = (const float*)d_in[16];
    const float* w2         = (const float*)d_in[17];
    const float* b2         = (const float*)d_in[18];
    float* out = (float*)d_out;

    float *p_qout, *p_qkv, *p_ctx, *p_Wf, *p_bf, *p_tmp, *p_h, *p_hidden;
    cudaGetSymbolAddress((void**)&p_qout,   g_qout);
    cudaGetSymbolAddress((void**)&p_qkv,    g_qkv);
    cudaGetSymbolAddress((void**)&p_ctx,    g_ctx);
    cudaGetSymbolAddress((void**)&p_Wf,     g_Wf);
    cudaGetSymbolAddress((void**)&p_bf,     g_bf);
    cudaGetSymbolAddress((void**)&p_tmp,    g_tmp);
    cudaGetSymbolAddress((void**)&p_h,      g_h);
    cudaGetSymbolAddress((void**)&p_hidden, g_hidden);

    // 1. q_out = cos(x + theta)
    cos_encode_kernel<<<(M_ * E_) / 1024, 256>>>(x, theta_attn);

    // 2. fold w_comb @ w_out
    fold_w_kernel<<<E_, 256>>>(w_comb, w_out, b_out, b_comb);

    // 3. qkv = q_out @ w_in^T + b_in      [4096 x 768]
    {
        dim3 grid((3 * E_) / 64, M_ / 128);
        sgemm2_kernel<<<grid, 256>>>(p_qout, w_in, b_in, p_qkv,
                                     M_, 3 * E_, E_, 0);
    }

    // 4a. attention pass 1 (split-K partials, no-max softmax)
    {
        dim3 grid(4, 2, B_ * H_);
        attn_p1_kernel<<<grid, 256>>>();
    }
    // 4b. attention pass 2 (sum + normalize) -> ctx
    attn_p2_kernel<<<(B_ * H_ * 512) / 256, 256>>>();

    // 5. attn_out = ctx @ Wf^T + bf       [4096 x 256]
    {
        dim3 grid(E_ / 64, M_ / 128);
        sgemm2_kernel<<<grid, 256>>>(p_ctx, p_Wf, p_bf, p_tmp,
                                     M_, E_, E_, 0);
    }

    // 6. h = LN(x + attn_out) * g1 + be1
    ln_kernel<<<M_ / 8, 256>>>(x, p_tmp, g1, be1, p_h);

    // 7. qf = cos(theta_ffn) * cos(h @ w_ip^T + b_ip)
    qf_kernel<<<M_, 256>>>(w_ip, b_ip, theta_ffn);

    // 8. hidden = relu(qf @ w1^T + b1)    [4096 x 1024]
    hidden_kernel<<<M_ * 4, 256>>>(w1, b1);

    // 9. ffn_out = hidden @ w2^T + b2     [4096 x 256]
    {
        dim3 grid(E_ / 64, M_ / 128);
        sgemm2_kernel<<<grid, 256>>>(p_hidden, w2, b2, p_tmp,
                                     M_, E_, FF_, 0);
    }

    // 10. out = LN(h + ffn_out) * g2 + be2
    ln_kernel<<<M_ / 8, 256>>>(p_h, p_tmp, g2, be2, out);
}

// round 5
// speedup vs baseline: 1.2684x; 1.2684x over previous
#include <cuda_runtime.h>
#include <math.h>
#include <stdint.h>

// Problem constants
#define B_   4
#define S_   1024
#define E_   256
#define H_   32
#define DK_  8
#define NQ_  8
#define FF_  1024
#define M_   (B_ * S_)   // 4096

typedef unsigned long long ULL;

// ---------------- f32x2 packed math helpers (PTX-only on sm_103a) ----------
__device__ __forceinline__ ULL fma2(ULL a, ULL b, ULL c) {
    ULL d; asm("fma.rn.f32x2 %0, %1, %2, %3;" : "=l"(d) : "l"(a), "l"(b), "l"(c)); return d;
}
__device__ __forceinline__ ULL mul2(ULL a, ULL b) {
    ULL d; asm("mul.rn.f32x2 %0, %1, %2;" : "=l"(d) : "l"(a), "l"(b)); return d;
}
__device__ __forceinline__ ULL add2(ULL a, ULL b) {
    ULL d; asm("add.rn.f32x2 %0, %1, %2;" : "=l"(d) : "l"(a), "l"(b)); return d;
}
__device__ __forceinline__ ULL pk(float lo, float hi) {
    ULL r; asm("mov.b64 %0, {%1, %2};" : "=l"(r) : "f"(lo), "f"(hi)); return r;
}
__device__ __forceinline__ void unpk(ULL v, float& lo, float& hi) {
    asm("mov.b64 {%0, %1}, %2;" : "=f"(lo), "=f"(hi) : "l"(v));
}
__device__ __forceinline__ float ex2f_(float x) {
    float y; asm("ex2.approx.f32 %0, %1;" : "=f"(y) : "f"(x)); return y;
}

// ---------------- scratch (device globals; no runtime allocation) ----------
__device__ __align__(16) float g_qout[M_ * E_];
__device__ __align__(16) float g_qkv[M_ * 3 * E_];
__device__ __align__(16) float g_ctx[M_ * E_];
__device__ __align__(16) float g_Wf[E_ * E_];
__device__ __align__(16) float g_bf[E_];
__device__ __align__(16) float g_tmp[M_ * E_];
__device__ __align__(16) float g_h[M_ * E_];
__device__ __align__(16) float g_qf[M_ * NQ_];
__device__ __align__(16) float g_hidden[M_ * FF_];
// split-K attention partials (no-max softmax).
// pidx = ((bh*4 + kq)*2 + qh)*128 + t ; thread covers queries
// qh*512 + t + {0,128} (pair A) and + {256,384} (pair B).
__device__ __align__(16) ULL g_pl[131072 * 2];              // (lA, lB)
__device__ __align__(16) ULL g_pacc[(size_t)131072 * 16];   // accA[8], accB[8]

// ---------------- q_out = cos(x + theta[e % 8]), float4 --------------------
__global__ __launch_bounds__(256) void cos_encode_kernel(
    const float* __restrict__ x, const float* __restrict__ theta)
{
    int i = (blockIdx.x * 256 + threadIdx.x) * 4;
    float4 v = *(const float4*)(x + i);
    int j = i & 7;
    v.x = __cosf(v.x + theta[j + 0]);
    v.y = __cosf(v.y + theta[j + 1]);
    v.z = __cosf(v.z + theta[j + 2]);
    v.w = __cosf(v.w + theta[j + 3]);
    *(float4*)(g_qout + i) = v;
}

// ---------------- fold: Wf = w_comb @ w_out, bf = w_comb@b_out + b_comb -----
__global__ __launch_bounds__(256) void fold_w_kernel(
    const float* __restrict__ w_comb, const float* __restrict__ w_out,
    const float* __restrict__ b_out, const float* __restrict__ b_comb)
{
    int i = blockIdx.x;
    int j = threadIdx.x;
    float s = 0.f;
    #pragma unroll 8
    for (int k = 0; k < E_; k++)
        s = fmaf(w_comb[i * E_ + k], w_out[k * E_ + j], s);
    g_Wf[i * E_ + j] = s;

    __shared__ float red[256];
    red[j] = w_comb[i * E_ + j] * b_out[j];
    __syncthreads();
    #pragma unroll
    for (int off = 128; off > 0; off >>= 1) {
        if (j < off) red[j] += red[j + off];
        __syncthreads();
    }
    if (j == 0) g_bf[i] = red[0] + b_comb[i];
}

// ---------------- f32x2 SGEMM (R3 version): C = A @ Bw^T + bias ------------
// BM=128, BN=64, BK=16, 256 threads, 8x4 microtile.
__global__ __launch_bounds__(256) void sgemm2_kernel(
    const float* __restrict__ A, const float* __restrict__ Bw,
    const float* __restrict__ bias, float* __restrict__ C,
    int M, int N, int K, int relu)
{
    __shared__ float As[16][132];
    __shared__ float Bs[16][68];

    int tid = threadIdx.x;
    int bm = blockIdx.y * 128;
    int bn = blockIdx.x * 64;
    int ty = tid >> 4;
    int tx = tid & 15;

    int alr = tid >> 1;
    int alc = (tid & 1) * 8;
    int blr = tid >> 2;
    int blc = (tid & 3) * 4;

    const float* Aptr = A  + (size_t)(bm + alr) * K + alc;
    const float* Bptr = Bw + (size_t)(bn + blr) * K + blc;

    float4 a0 = *(const float4*)(Aptr);
    float4 a1 = *(const float4*)(Aptr + 4);
    float4 b0 = *(const float4*)(Bptr);

    ULL acc[4][4];
    #pragma unroll
    for (int r = 0; r < 4; r++)
        #pragma unroll
        for (int j = 0; j < 4; j++) acc[r][j] = 0ULL;

    for (int k0 = 0; ; k0 += 16) {
        As[alc + 0][alr] = a0.x; As[alc + 1][alr] = a0.y;
        As[alc + 2][alr] = a0.z; As[alc + 3][alr] = a0.w;
        As[alc + 4][alr] = a1.x; As[alc + 5][alr] = a1.y;
        As[alc + 6][alr] = a1.z; As[alc + 7][alr] = a1.w;
        Bs[blc + 0][blr] = b0.x; Bs[blc + 1][blr] = b0.y;
        Bs[blc + 2][blr] = b0.z; Bs[blc + 3][blr] = b0.w;
        __syncthreads();

        bool last = (k0 + 16 >= K);
        if (!last) {
            Aptr += 16; Bptr += 16;
            a0 = *(const float4*)(Aptr);
            a1 = *(const float4*)(Aptr + 4);
            b0 = *(const float4*)(Bptr);
        }

        #pragma unroll
        for (int kk = 0; kk < 16; kk++) {
            ulonglong2 am0 = *(const ulonglong2*)&As[kk][ty * 8];
            ulonglong2 am1 = *(const ulonglong2*)&As[kk][ty * 8 + 4];
            float4 b4 = *(const float4*)&Bs[kk][tx * 4];
            ULL bb0 = pk(b4.x, b4.x), bb1 = pk(b4.y, b4.y);
            ULL bb2 = pk(b4.z, b4.z), bb3 = pk(b4.w, b4.w);
            ULL am[4] = {am0.x, am0.y, am1.x, am1.y};
            #pragma unroll
            for (int r = 0; r < 4; r++) {
                acc[r][0] = fma2(am[r], bb0, acc[r][0]);
                acc[r][1] = fma2(am[r], bb1, acc[r][1]);
                acc[r][2] = fma2(am[r], bb2, acc[r][2]);
                acc[r][3] = fma2(am[r], bb3, acc[r][3]);
            }
        }
        if (last) break;
        __syncthreads();
    }

    int col = bn + tx * 4;
    float4 bb = *(const float4*)(bias + col);
    #pragma unroll
    for (int r = 0; r < 4; r++) {
        float lo0, hi0, lo1, hi1, lo2v, hi2, lo3, hi3;
        unpk(acc[r][0], lo0, hi0);
        unpk(acc[r][1], lo1, hi1);
        unpk(acc[r][2], lo2v, hi2);
        unpk(acc[r][3], lo3, hi3);
        int row0 = bm + ty * 8 + 2 * r;
        float4 v;
        v.x = lo0 + bb.x; v.y = lo1 + bb.y; v.z = lo2v + bb.z; v.w = lo3 + bb.w;
        if (relu) { v.x = fmaxf(v.x, 0.f); v.y = fmaxf(v.y, 0.f);
                    v.z = fmaxf(v.z, 0.f); v.w = fmaxf(v.w, 0.f); }
        *(float4*)(C + (size_t)row0 * N + col) = v;
        v.x = hi0 + bb.x; v.y = hi1 + bb.y; v.z = hi2 + bb.z; v.w = hi3 + bb.w;
        if (relu) { v.x = fmaxf(v.x, 0.f); v.y = fmaxf(v.y, 0.f);
                    v.z = fmaxf(v.z, 0.f); v.w = fmaxf(v.w, 0.f); }
        *(float4*)(C + (size_t)(row0 + 1) * N + col) = v;
    }
}

// ---------------- attention pass 1: split-K, no-max softmax, 4 q/thread -----
// grid = (4 key-quarters, 2 query-halves, 128 bh), 128 threads.
// K/V duplicated (k,k) in smem; q packed across queries (2 pairs per thread).
__global__ __launch_bounds__(128) void attn_p1_kernel()
{
    __shared__ ULL Kd[256 * 8];   // 16 KB, Kd[s*8+c] = (k_s[c], k_s[c])
    __shared__ ULL Vd[256 * 8];   // 16 KB

    int kq = blockIdx.x;
    int qh = blockIdx.y;
    int bh = blockIdx.z;
    int b = bh >> 5;
    int h = bh & 31;
    int t = threadIdx.x;
    const float* base = g_qkv + (size_t)b * S_ * (3 * E_) + h * DK_;

    // stage: 2 keys per thread, duplicated
    #pragma unroll
    for (int rep = 0; rep < 2; rep++) {
        int sk = rep * 128 + t;
        const float* rowp = base + (size_t)(kq * 256 + sk) * (3 * E_);
        float4 k0 = *(const float4*)(rowp + E_);
        float4 k1 = *(const float4*)(rowp + E_ + 4);
        float4 v0 = *(const float4*)(rowp + 2 * E_);
        float4 v1 = *(const float4*)(rowp + 2 * E_ + 4);
        ulonglong2* kr = (ulonglong2*)(Kd + sk * 8);
        ulonglong2* vr = (ulonglong2*)(Vd + sk * 8);
        kr[0] = make_ulonglong2(pk(k0.x, k0.x), pk(k0.y, k0.y));
        kr[1] = make_ulonglong2(pk(k0.z, k0.z), pk(k0.w, k0.w));
        kr[2] = make_ulonglong2(pk(k1.x, k1.x), pk(k1.y, k1.y));
        kr[3] = make_ulonglong2(pk(k1.z, k1.z), pk(k1.w, k1.w));
        vr[0] = make_ulonglong2(pk(v0.x, v0.x), pk(v0.y, v0.y));
        vr[1] = make_ulonglong2(pk(v0.z, v0.z), pk(v0.w, v0.w));
        vr[2] = make_ulonglong2(pk(v1.x, v1.x), pk(v1.y, v1.y));
        vr[3] = make_ulonglong2(pk(v1.z, v1.z), pk(v1.w, v1.w));
    }
    __syncthreads();

    const float qscale = 0.35355339059327373f * 1.4426950408889634f; // log2e/sqrt(8)

    // 4 queries: pair A = (qh*512+t, +128), pair B = (+256, +384)
    ULL qA[8], qB[8];
    {
        const float* r0 = base + (size_t)(qh * 512 + t)       * (3 * E_);
        const float* r1 = base + (size_t)(qh * 512 + t + 128) * (3 * E_);
        const float* r2 = base + (size_t)(qh * 512 + t + 256) * (3 * E_);
        const float* r3 = base + (size_t)(qh * 512 + t + 384) * (3 * E_);
        float4 a0 = *(const float4*)(r0), a1 = *(const float4*)(r0 + 4);
        float4 b0 = *(const float4*)(r1), b1 = *(const float4*)(r1 + 4);
        float4 c0 = *(const float4*)(r2), c1 = *(const float4*)(r2 + 4);
        float4 d0 = *(const float4*)(r3), d1 = *(const float4*)(r3 + 4);
        qA[0] = pk(a0.x * qscale, b0.x * qscale);
        qA[1] = pk(a0.y * qscale, b0.y * qscale);
        qA[2] = pk(a0.z * qscale, b0.z * qscale);
        qA[3] = pk(a0.w * qscale, b0.w * qscale);
        qA[4] = pk(a1.x * qscale, b1.x * qscale);
        qA[5] = pk(a1.y * qscale, b1.y * qscale);
        qA[6] = pk(a1.z * qscale, b1.z * qscale);
        qA[7] = pk(a1.w * qscale, b1.w * qscale);
        qB[0] = pk(c0.x * qscale, d0.x * qscale);
        qB[1] = pk(c0.y * qscale, d0.y * qscale);
        qB[2] = pk(c0.z * qscale, d0.z * qscale);
        qB[3] = pk(c0.w * qscale, d0.w * qscale);
        qB[4] = pk(c1.x * qscale, d1.x * qscale);
        qB[5] = pk(c1.y * qscale, d1.y * qscale);
        qB[6] = pk(c1.z * qscale, d1.z * qscale);
        qB[7] = pk(c1.w * qscale, d1.w * qscale);
    }

    ULL lA = 0ULL, lB = 0ULL;
    ULL accA[8], accB[8];
    #pragma unroll
    for (int c = 0; c < 8; c++) { accA[c] = 0ULL; accB[c] = 0ULL; }

    #pragma unroll 2
    for (int s = 0; s < 256; s++) {
        const ulonglong2* kr = (const ulonglong2*)(Kd + s * 8);
        ulonglong2 k01 = kr[0], k23 = kr[1], k45 = kr[2], k67 = kr[3];

        ULL tA = mul2(qA[0], k01.x);
        ULL tB = mul2(qB[0], k01.x);
        tA = fma2(qA[1], k01.y, tA);
        tB = fma2(qB[1], k01.y, tB);
        tA = fma2(qA[2], k23.x, tA);
        tB = fma2(qB[2], k23.x, tB);
        tA = fma2(qA[3], k23.y, tA);
        tB = fma2(qB[3], k23.y, tB);
        tA = fma2(qA[4], k45.x, tA);
        tB = fma2(qB[4], k45.x, tB);
        tA = fma2(qA[5], k45.y, tA);
        tB = fma2(qB[5], k45.y, tB);
        tA = fma2(qA[6], k67.x, tA);
        tB = fma2(qB[6], k67.x, tB);
        tA = fma2(qA[7], k67.y, tA);
        tB = fma2(qB[7], k67.y, tB);

        float dA0, dA1, dB0, dB1;
        unpk(tA, dA0, dA1);
        unpk(tB, dB0, dB1);
        ULL ppA = pk(ex2f_(dA0), ex2f_(dA1));
        ULL ppB = pk(ex2f_(dB0), ex2f_(dB1));
        lA = add2(lA, ppA);
        lB = add2(lB, ppB);

        const ulonglong2* vr = (const ulonglong2*)(Vd + s * 8);
        ulonglong2 v01 = vr[0], v23 = vr[1], v45 = vr[2], v67 = vr[3];
        accA[0] = fma2(ppA, v01.x, accA[0]);
        accB[0] = fma2(ppB, v01.x, accB[0]);
        accA[1] = fma2(ppA, v01.y, accA[1]);
        accB[1] = fma2(ppB, v01.y, accB[1]);
        accA[2] = fma2(ppA, v23.x, accA[2]);
        accB[2] = fma2(ppB, v23.x, accB[2]);
        accA[3] = fma2(ppA, v23.y, accA[3]);
        accB[3] = fma2(ppB, v23.y, accB[3]);
        accA[4] = fma2(ppA, v45.x, accA[4]);
        accB[4] = fma2(ppB, v45.x, accB[4]);
        accA[5] = fma2(ppA, v45.y, accA[5]);
        accB[5] = fma2(ppB, v45.y, accB[5]);
        accA[6] = fma2(ppA, v67.x, accA[6]);
        accB[6] = fma2(ppB, v67.x, accB[6]);
        accA[7] = fma2(ppA, v67.y, accA[7]);
        accB[7] = fma2(ppB, v67.y, accB[7]);
    }

    int pidx = ((bh * 4 + kq) * 2 + qh) * 128 + t;
    ((ulonglong2*)g_pl)[pidx] = make_ulonglong2(lA, lB);
    ulonglong2* pa = (ulonglong2*)(g_pacc + (size_t)pidx * 16);
    pa[0] = make_ulonglong2(accA[0], accA[1]);
    pa[1] = make_ulonglong2(accA[2], accA[3]);
    pa[2] = make_ulonglong2(accA[4], accA[5]);
    pa[3] = make_ulonglong2(accA[6], accA[7]);
    pa[4] = make_ulonglong2(accB[0], accB[1]);
    pa[5] = make_ulonglong2(accB[2], accB[3]);
    pa[6] = make_ulonglong2(accB[4], accB[5]);
    pa[7] = make_ulonglong2(accB[6], accB[7]);
}

// ---------------- attention pass 2: sum 4 partials, normalize, 4 q/thread ---
__global__ __launch_bounds__(256) void attn_p2_kernel()
{
    int idx = blockIdx.x * 256 + threadIdx.x;   // 32768 threads
    int bh = idx >> 8;
    int r  = idx & 255;
    int qh = r >> 7;
    int t  = r & 127;
    int b = bh >> 5;
    int h = bh & 31;

    ULL lA = 0ULL, lB = 0ULL;
    ULL cA[8], cB[8];
    #pragma unroll
    for (int j = 0; j < 8; j++) { cA[j] = 0ULL; cB[j] = 0ULL; }

    #pragma unroll
    for (int kq = 0; kq < 4; kq++) {
        int pidx = ((bh * 4 + kq) * 2 + qh) * 128 + t;
        ulonglong2 lp = ((const ulonglong2*)g_pl)[pidx];
        lA = add2(lA, lp.x);
        lB = add2(lB, lp.y);
        const ulonglong2* pa = (const ulonglong2*)(g_pacc + (size_t)pidx * 16);
        ulonglong2 a0 = pa[0], a1 = pa[1], a2 = pa[2], a3 = pa[3];
        ulonglong2 b0 = pa[4], b1 = pa[5], b2 = pa[6], b3 = pa[7];
        cA[0] = add2(cA[0], a0.x); cA[1] = add2(cA[1], a0.y);
        cA[2] = add2(cA[2], a1.x); cA[3] = add2(cA[3], a1.y);
        cA[4] = add2(cA[4], a2.x); cA[5] = add2(cA[5], a2.y);
        cA[6] = add2(cA[6], a3.x); cA[7] = add2(cA[7], a3.y);
        cB[0] = add2(cB[0], b0.x); cB[1] = add2(cB[1], b0.y);
        cB[2] = add2(cB[2], b1.x); cB[3] = add2(cB[3], b1.y);
        cB[4] = add2(cB[4], b2.x); cB[5] = add2(cB[5], b2.y);
        cB[6] = add2(cB[6], b3.x); cB[7] = add2(cB[7], b3.y);
    }

    float LA0, LA1, LB0, LB1;
    unpk(lA, LA0, LA1);
    unpk(lB, LB0, LB1);
    float r0 = 1.f / LA0, r1 = 1.f / LA1, r2 = 1.f / LB0, r3 = 1.f / LB1;

    int q0 = qh * 512 + t;
    float* o0 = g_ctx + ((size_t)b * S_ + q0)       * E_ + h * DK_;
    float* o1 = g_ctx + ((size_t)b * S_ + q0 + 128) * E_ + h * DK_;
    float* o2 = g_ctx + ((size_t)b * S_ + q0 + 256) * E_ + h * DK_;
    float* o3 = g_ctx + ((size_t)b * S_ + q0 + 384) * E_ + h * DK_;

    float xA0[8], xA1[8], xB0[8], xB1[8];
    #pragma unroll
    for (int j = 0; j < 8; j++) { unpk(cA[j], xA0[j], xA1[j]); unpk(cB[j], xB0[j], xB1[j]); }
    float4 w;
    w.x = xA0[0]*r0; w.y = xA0[1]*r0; w.z = xA0[2]*r0; w.w = xA0[3]*r0;
    *(float4*)(o0) = w;
    w.x = xA0[4]*r0; w.y = xA0[5]*r0; w.z = xA0[6]*r0; w.w = xA0[7]*r0;
    *(float4*)(o0 + 4) = w;
    w.x = xA1[0]*r1; w.y = xA1[1]*r1; w.z = xA1[2]*r1; w.w = xA1[3]*r1;
    *(float4*)(o1) = w;
    w.x = xA1[4]*r1; w.y = xA1[5]*r1; w.z = xA1[6]*r1; w.w = xA1[7]*r1;
    *(float4*)(o1 + 4) = w;
    w.x = xB0[0]*r2; w.y = xB0[1]*r2; w.z = xB0[2]*r2; w.w = xB0[3]*r2;
    *(float4*)(o2) = w;
    w.x = xB0[4]*r2; w.y = xB0[5]*r2; w.z = xB0[6]*r2; w.w = xB0[7]*r2;
    *(float4*)(o2 + 4) = w;
    w.x = xB1[0]*r3; w.y = xB1[1]*r3; w.z = xB1[2]*r3; w.w = xB1[3]*r3;
    *(float4*)(o3) = w;
    w.x = xB1[4]*r3; w.y = xB1[5]*r3; w.z = xB1[6]*r3; w.w = xB1[7]*r3;
    *(float4*)(o3 + 4) = w;
}

// ---------------- layernorm: out = LN(a + b) * g + beta  (warp per row) -----
__global__ __launch_bounds__(256) void ln_kernel(
    const float* __restrict__ a, const float* __restrict__ bsrc,
    const float* __restrict__ g, const float* __restrict__ beta,
    float* __restrict__ out)
{
    int row  = (blockIdx.x * 256 + threadIdx.x) >> 5;
    int lane = threadIdx.x & 31;
    size_t off = (size_t)row * E_ + lane * 8;

    const float4* ap = (const float4*)(a + off);
    const float4* bp = (const float4*)(bsrc + off);
    float4 a0 = ap[0], a1 = ap[1], b0 = bp[0], b1 = bp[1];
    float v[8];
    v[0] = a0.x + b0.x; v[1] = a0.y + b0.y; v[2] = a0.z + b0.z; v[3] = a0.w + b0.w;
    v[4] = a1.x + b1.x; v[5] = a1.y + b1.y; v[6] = a1.z + b1.z; v[7] = a1.w + b1.w;

    float s = 0.f, ss = 0.f;
    #pragma unroll
    for (int i = 0; i < 8; i++) { s += v[i]; ss = fmaf(v[i], v[i], ss); }
    #pragma unroll
    for (int o = 16; o > 0; o >>= 1) {
        s  += __shfl_xor_sync(0xFFFFFFFFu, s,  o);
        ss += __shfl_xor_sync(0xFFFFFFFFu, ss, o);
    }
    float mu  = s * (1.f / E_);
    float var = ss * (1.f / E_) - mu * mu;
    float rs  = rsqrtf(var + 1e-5f);

    const float4* gp  = (const float4*)(g    + lane * 8);
    const float4* bep = (const float4*)(beta + lane * 8);
    float4 g0 = gp[0], g1v = gp[1], e0 = bep[0], e1 = bep[1];

    float4 w;
    w.x = (v[0]-mu)*rs*g0.x + e0.x; w.y = (v[1]-mu)*rs*g0.y + e0.y;
    w.z = (v[2]-mu)*rs*g0.z + e0.z; w.w = (v[3]-mu)*rs*g0.w + e0.w;
    *(float4*)(out + off) = w;
    w.x = (v[4]-mu)*rs*g1v.x + e1.x; w.y = (v[5]-mu)*rs*g1v.y + e1.y;
    w.z = (v[6]-mu)*rs*g1v.z + e1.z; w.w = (v[7]-mu)*rs*g1v.w + e1.w;
    *(float4*)(out + off + 4) = w;
}

// ---------------- qf = cos(theta_ffn) * cos(h @ w_ip^T + b_ip) --------------
__global__ __launch_bounds__(256) void qf_kernel(
    const float* __restrict__ w_ip, const float* __restrict__ b_ip,
    const float* __restrict__ theta_ffn)
{
    int m    = blockIdx.x;
    int j    = threadIdx.x >> 5;
    int lane = threadIdx.x & 31;
    const float* hr = g_h + (size_t)m * E_;
    const float* wr = w_ip + (size_t)j * E_;
    float s = 0.f;
    #pragma unroll
    for (int e = 0; e < E_; e += 32)
        s = fmaf(hr[e + lane], wr[e + lane], s);
    #pragma unroll
    for (int o = 16; o > 0; o >>= 1)
        s += __shfl_xor_sync(0xFFFFFFFFu, s, o);
    if (lane == 0)
        g_qf[m * NQ_ + j] = __cosf(theta_ffn[j]) * __cosf(s + b_ip[j]);
}

// ---------------- hidden = relu(qf @ w1^T + b1)   (K=8) ---------------------
__global__ __launch_bounds__(256) void hidden_kernel(
    const float* __restrict__ w1, const float* __restrict__ b1)
{
    int m = blockIdx.x >> 2;
    int f = ((blockIdx.x & 3) << 8) + threadIdx.x;
    const float* qr = g_qf + (size_t)m * NQ_;
    const float* wr = w1 + (size_t)f * NQ_;
    float s = b1[f];
    #pragma unroll
    for (int j = 0; j < NQ_; j++)
        s = fmaf(qr[j], wr[j], s);
    g_hidden[(size_t)m * FF_ + f] = fmaxf(s, 0.f);
}

// ---------------- launch ----------------------------------------------------
extern "C" void kernel_launch(void* const* d_in, const int* in_sizes, int n_in,
                              void* d_out, int out_size)
{
    (void)in_sizes; (void)n_in; (void)out_size;

    const float* x          = (const float*)d_in[0];
    const float* theta_attn = (const float*)d_in[1];
    const float* w_in       = (const float*)d_in[2];
    const float* b_in       = (const float*)d_in[3];
    const float* w_out      = (const float*)d_in[4];
    const float* b_out      = (const float*)d_in[5];
    const float* w_comb     = (const float*)d_in[6];
    const float* b_comb     = (const float*)d_in[7];
    const float* g1         = (const float*)d_in[8];
    const float* be1        = (const float*)d_in[9];
    const float* g2         = (const float*)d_in[10];
    const float* be2        = (const float*)d_in[11];
    const float* w_ip       = (const float*)d_in[12];
    const float* b_ip       = (const float*)d_in[13];
    const float* theta_ffn  = (const float*)d_in[14];
    const float* w1         = (const float*)d_in[15];
    const float* b1         = (const float*)d_in[16];
    const float* w2         = (const float*)d_in[17];
    const float* b2         = (const float*)d_in[18];
    float* out = (float*)d_out;

    float *p_qout, *p_qkv, *p_ctx, *p_Wf, *p_bf, *p_tmp, *p_h, *p_hidden;
    cudaGetSymbolAddress((void**)&p_qout,   g_qout);
    cudaGetSymbolAddress((void**)&p_qkv,    g_qkv);
    cudaGetSymbolAddress((void**)&p_ctx,    g_ctx);
    cudaGetSymbolAddress((void**)&p_Wf,     g_Wf);
    cudaGetSymbolAddress((void**)&p_bf,     g_bf);
    cudaGetSymbolAddress((void**)&p_tmp,    g_tmp);
    cudaGetSymbolAddress((void**)&p_h,      g_h);
    cudaGetSymbolAddress((void**)&p_hidden, g_hidden);

    // 1. q_out = cos(x + theta)
    cos_encode_kernel<<<(M_ * E_) / 1024, 256>>>(x, theta_attn);

    // 2. fold w_comb @ w_out
    fold_w_kernel<<<E_, 256>>>(w_comb, w_out, b_out, b_comb);

    // 3. qkv = q_out @ w_in^T + b_in      [4096 x 768]
    {
        dim3 grid((3 * E_) / 64, M_ / 128);
        sgemm2_kernel<<<grid, 256>>>(p_qout, w_in, b_in, p_qkv,
                                     M_, 3 * E_, E_, 0);
    }

    // 4a. attention pass 1 (split-K partials)
    {
        dim3 grid(4, 2, B_ * H_);
        attn_p1_kernel<<<grid, 128>>>();
    }
    // 4b. attention pass 2 (sum + normalize) -> ctx
    attn_p2_kernel<<<128, 256>>>();

    // 5. attn_out = ctx @ Wf^T + bf       [4096 x 256]
    {
        dim3 grid(E_ / 64, M_ / 128);
        sgemm2_kernel<<<grid, 256>>>(p_ctx, p_Wf, p_bf, p_tmp,
                                     M_, E_, E_, 0);
    }

    // 6. h = LN(x + attn_out) * g1 + be1
    ln_kernel<<<M_ / 8, 256>>>(x, p_tmp, g1, be1, p_h);

    // 7. qf = cos(theta_ffn) * cos(h @ w_ip^T + b_ip)
    qf_kernel<<<M_, 256>>>(w_ip, b_ip, theta_ffn);

    // 8. hidden = relu(qf @ w1^T + b1)    [4096 x 1024]
    hidden_kernel<<<M_ * 4, 256>>>(w1, b1);

    // 9. ffn_out = hidden @ w2^T + b2     [4096 x 256]
    {
        dim3 grid(E_ / 64, M_ / 128);
        sgemm2_kernel<<<grid, 256>>>(p_hidden, w2, b2, p_tmp,
                                     M_, E_, FF_, 0);
    }

    // 10. out = LN(h + ffn_out) * g2 + be2
    ln_kernel<<<M_ / 8, 256>>>(p_h, p_tmp, g2, be2, out);
}